// round 2
// baseline (speedup 1.0000x reference)
#include <cuda_runtime.h>

#define BB 4
#define NCH 3
#define NCLS 20
#define HH 512
#define WW 512
#define MAXB 50
#define STRIPS 16
#define THREADS 256

__device__ float g_acc;

__global__ void sel_zero_kernel() { g_acc = 0.0f; }

__global__ void sel_box_kernel(const float* __restrict__ y_fcn,
                               const float* __restrict__ im_data,
                               const int* __restrict__ gt_boxes,
                               const int* __restrict__ num_boxes) {
    const int boxid = blockIdx.x;          // 0 .. B*MAXB-1
    const int b = boxid / MAXB;
    const int j = boxid % MAXB;
    if (j >= num_boxes[b]) return;         // invalid box contributes 0

    const int* g = gt_boxes + (size_t)boxid * 5;
    const int x1 = g[0], y1 = g[1], x2 = g[2], y2 = g[3], cls = g[4];
    const int hgt = y2 - y1;
    const int wid = x2 - x1;
    if (hgt <= 0 || wid <= 0) return;

    // row strip for this CTA
    const int rows_per = (hgt + STRIPS - 1) / STRIPS;
    const int r0 = y1 + blockIdx.y * rows_per;
    const int r1 = min(r0 + rows_per, y2);
    if (r0 >= r1) return;

    const size_t plane = (size_t)HH * WW;
    const float* im0 = im_data + (size_t)b * NCH * plane;
    const float* yf0 = y_fcn + ((size_t)b * NCLS + cls) * NCH * plane;

    float acc = 0.0f;
    const int total = (r1 - r0) * wid;
    for (int idx = threadIdx.x; idx < total; idx += THREADS) {
        const int rr = idx / wid;
        const int cc = idx - rr * wid;
        const int off = (r0 + rr) * WW + x1 + cc;
#pragma unroll
        for (int n = 0; n < NCH; n++) {
            const float d = __ldg(im0 + (size_t)n * plane + off)
                          - __ldg(yf0 + (size_t)n * plane + off);
            acc += d * d;
        }
    }

    // block reduction
    __shared__ float sm[THREADS / 32];
#pragma unroll
    for (int o = 16; o > 0; o >>= 1)
        acc += __shfl_down_sync(0xffffffffu, acc, o);
    const int lane = threadIdx.x & 31;
    const int warp = threadIdx.x >> 5;
    if (lane == 0) sm[warp] = acc;
    __syncthreads();
    if (warp == 0) {
        acc = (lane < THREADS / 32) ? sm[lane] : 0.0f;
#pragma unroll
        for (int o = (THREADS / 64); o > 0; o >>= 1)
            acc += __shfl_down_sync(0xffffffffu, acc, o);
        if (lane == 0) {
            const float denom = (float)(NCH * max(hgt * wid, 1));
            atomicAdd(&g_acc, acc / denom);
        }
    }
}

__global__ void sel_final_kernel(const int* __restrict__ num_boxes,
                                 float* __restrict__ out) {
    int s = 0;
#pragma unroll
    for (int b = 0; b < BB; b++) s += num_boxes[b];
    out[0] = g_acc / (float)s;
}

extern "C" void kernel_launch(void* const* d_in, const int* in_sizes, int n_in,
                              void* d_out, int out_size) {
    const float* y_fcn    = (const float*)d_in[0];  // [B, NCH*NCLS, H, W]
    const float* im_data  = (const float*)d_in[1];  // [B, NCH, H, W]
    // d_in[2] = im_info (unused)
    const int*   gt_boxes = (const int*)d_in[3];    // [B, MAXB, 5]
    const int*   num_boxes= (const int*)d_in[4];    // [B]
    float*       out      = (float*)d_out;

    sel_zero_kernel<<<1, 1>>>();
    dim3 grid(BB * MAXB, STRIPS);
    sel_box_kernel<<<grid, THREADS>>>(y_fcn, im_data, gt_boxes, num_boxes);
    sel_final_kernel<<<1, 1>>>(num_boxes, out);
}